// round 1
// baseline (speedup 1.0000x reference)
#include <cuda_runtime.h>
#include <cstdint>

// Problem constants
#define NB 64
#define C  128
#define H  56
#define W  56
#define HW (H*W)

// Scratch (static __device__ -> no allocation, graph-capturable)
__device__ uint4  g_xbits[NB * HW];      // [n][h][w] -> 128 sign bits (4 words), bit=1 iff x<0
__device__ __align__(16) uint32_t g_wbits[C * 9 * 4]; // [co][tap][word], bit=1 iff w<0
__device__ float  g_A[C];                // scale_o * gamma * rsqrt(var+eps)
__device__ float  g_B[C];                // beta - mean * gamma * rsqrt(var+eps)

// ---------------------------------------------------------------------------
// Kernel 1: pack sign(x) bits. One thread per pixel, loops 128 channels
// (coalesced across threads for each channel iteration).
// ---------------------------------------------------------------------------
__global__ void pack_kernel(const float* __restrict__ x) {
    int p = blockIdx.x * blockDim.x + threadIdx.x;
    if (p >= NB * HW) return;
    int n  = p / HW;
    int hw = p - n * HW;
    const float* xp = x + (size_t)n * C * HW + hw;
    uint32_t b0 = 0, b1 = 0, b2 = 0, b3 = 0;
#pragma unroll 8
    for (int c = 0; c < 32; c++) {
        b0 |= (__float_as_uint(__ldg(xp + (size_t)(c      ) * HW)) >> 31) << c;
        b1 |= (__float_as_uint(__ldg(xp + (size_t)(c + 32 ) * HW)) >> 31) << c;
        b2 |= (__float_as_uint(__ldg(xp + (size_t)(c + 64 ) * HW)) >> 31) << c;
        b3 |= (__float_as_uint(__ldg(xp + (size_t)(c + 96 ) * HW)) >> 31) << c;
    }
    g_xbits[p] = make_uint4(b0, b1, b2, b3);
}

// ---------------------------------------------------------------------------
// Kernel 2: weight prep. 512 threads: thread = (co, word j). Each thread
// handles 32 input channels x 9 taps; sabs reduced across the 4 j-lanes.
// ---------------------------------------------------------------------------
__global__ void wprep_kernel(const float* __restrict__ wgt,
                             const float* __restrict__ gamma,
                             const float* __restrict__ beta,
                             const float* __restrict__ mean,
                             const float* __restrict__ var) {
    int tid = threadIdx.x;            // 0..511
    int co  = tid >> 2;
    int j   = tid & 3;
    const float* wp = wgt + (size_t)co * (C * 9) + (size_t)(j * 32) * 9;

    uint32_t wb[9];
#pragma unroll
    for (int t = 0; t < 9; t++) wb[t] = 0;
    float sabs = 0.0f;

    for (int c = 0; c < 32; c++) {
#pragma unroll
        for (int t = 0; t < 9; t++) {
            uint32_t u = __float_as_uint(wp[c * 9 + t]);
            sabs += fabsf(__uint_as_float(u));
            wb[t] |= (u >> 31) << c;
        }
    }
    // reduce sabs across the 4 lanes of this co (lanes co*4 .. co*4+3 are
    // contiguous within a warp)
    sabs += __shfl_xor_sync(0xffffffffu, sabs, 1);
    sabs += __shfl_xor_sync(0xffffffffu, sabs, 2);

#pragma unroll
    for (int t = 0; t < 9; t++)
        g_wbits[(co * 9 + t) * 4 + j] = wb[t];

    if (j == 0) {
        float scale = sabs * (1.0f / 1152.0f);
        float inv   = gamma[co] * rsqrtf(var[co] + 1e-5f);
        g_A[co] = scale * inv;
        g_B[co] = beta[co] - mean[co] * inv;
    }
}

// ---------------------------------------------------------------------------
// Kernel 3: binary conv + BN + residual.
// CTA = (n, h): one output row, all 128 output channels. 256 threads:
//   warp&1 selects w-half (w = half*32 + lane), warp>>2.. -> chunk of 32 co.
// xbits rows (h-1,h,h+1) and all weight bits live in smem.
// ---------------------------------------------------------------------------
__global__ __launch_bounds__(256, 4)
void conv_kernel(const float* __restrict__ x, float* __restrict__ out) {
    int nb = blockIdx.x;
    int n  = nb / H;
    int h  = nb - n * H;

    __shared__ uint4 s_x[3 * W];
    __shared__ uint4 s_w[C * 9];
    __shared__ float s_A[C];
    __shared__ float s_B[C];

    int tid = threadIdx.x;

    // stage weights (L2-resident, tiny)
    const uint4* gw = (const uint4*)g_wbits;
    for (int i = tid; i < C * 9; i += 256) s_w[i] = gw[i];
    if (tid < C) { s_A[tid] = g_A[tid]; s_B[tid] = g_B[tid]; }

    bool rv0 = (h > 0), rv2 = (h < H - 1);
    // stage 3 xbit rows
    for (int i = tid; i < 3 * W; i += 256) {
        int r  = i / W;
        int ww = i - r * W;
        bool v = (r == 1) || (r == 0 ? rv0 : rv2);
        if (v) s_x[i] = g_xbits[(size_t)(n * H + (h - 1 + r)) * W + ww];
    }
    __syncthreads();

    int warp  = tid >> 5;
    int lane  = tid & 31;
    int half  = warp & 1;
    int chunk = warp >> 1;           // 0..3 -> 32 output channels each
    int w     = half * 32 + lane;
    if (w >= W) return;              // no syncs after this point

    // gather the 9 tap words for this pixel into registers
    uint4 xv[9];
    unsigned vmask = 0;
    int nvalid = 0;
#pragma unroll
    for (int t = 0; t < 9; t++) {
        const int dh = t / 3;        // 0..2
        const int dw = t % 3;        // 0..2
        int cw = w + dw - 1;
        bool rowok = (dh == 1) || (dh == 0 ? rv0 : rv2);
        bool v = rowok && (cw >= 0) && (cw < W);
        if (v) { xv[t] = s_x[dh * W + cw]; nvalid++; vmask |= (1u << t); }
        else   { xv[t] = make_uint4(0u, 0u, 0u, 0u); }
    }
    const int base = nvalid * 128;

    const float* resid = x   + ((size_t)n * C) * HW + (size_t)h * W + w;
    float*       outp  = out + ((size_t)n * C) * HW + (size_t)h * W + w;

    const int co0 = chunk * 32;
#pragma unroll 4
    for (int k = 0; k < 32; k++) {
        int co = co0 + k;
        // prefetch residual early to hide LDG latency under the popc chain
        float r = resid[(size_t)co * HW];
        int acc = 0;
#pragma unroll
        for (int t = 0; t < 9; t++) {
            if (vmask & (1u << t)) {
                uint4 wv = s_w[co * 9 + t];
                acc += __popc(xv[t].x ^ wv.x) + __popc(xv[t].y ^ wv.y)
                     + __popc(xv[t].z ^ wv.z) + __popc(xv[t].w ^ wv.w);
            }
        }
        float dot = (float)(base - 2 * acc);
        outp[(size_t)co * HW] = fmaf(dot, s_A[co], s_B[co]) + r;
    }
}

// ---------------------------------------------------------------------------
extern "C" void kernel_launch(void* const* d_in, const int* in_sizes, int n_in,
                              void* d_out, int out_size) {
    const float* x     = (const float*)d_in[0];
    const float* wgt   = (const float*)d_in[1];
    const float* gamma = (const float*)d_in[2];
    const float* beta  = (const float*)d_in[3];
    const float* mean  = (const float*)d_in[4];
    const float* var   = (const float*)d_in[5];
    float* out = (float*)d_out;

    (void)in_sizes; (void)n_in; (void)out_size;

    int npix = NB * HW;
    pack_kernel<<<(npix + 255) / 256, 256>>>(x);
    wprep_kernel<<<1, 512>>>(wgt, gamma, beta, mean, var);
    conv_kernel<<<NB * H, 256>>>(x, out);
}